// round 12
// baseline (speedup 1.0000x reference)
#include <cuda_runtime.h>
#include <cuda_bf16.h>

// Local Moran's I:
//   m = mean(X)
//   out_i = (x_i - m) * [sum_j w_ij (x_j - m)] * (K-1) / [sum_j w_ij (x_j - m)^2]
//
// N = 1,000,000, K = 32.
//
// Bottleneck (validated R6-R10): L1tex wavefront throughput in the gather
// kernel (~30 irreducible wavefronts/row -> ~115us floor; measured 119.5us,
// l1tex=87%). This round hides the ~4us serialized mean stage:
//   - mean-free main-loop algebra: A=sum(w x), B=sum(w x^2), C=sum(w);
//     lag = A - mC, S = B - 2mA + m^2 C (m ~ 1e-3, cancellation harmless)
//   - PDL: mean kernel triggers launch completion at entry; main kernel
//     overlaps its entire load phase with the mean and grid-syncs only
//     before the epilogue reads g_mean.
//   - Defensive: if the attributed launch is rejected, fall back to a plain
//     serialized launch (identical results; launch order independent).

#define KNBR 32
#define MEAN_BLOCKS 512

__device__ float g_partials[MEAN_BLOCKS];
__device__ float g_mean;
__device__ unsigned int g_ticket;  // zero-init; atomicInc wraps to 0 per run

// ---------------- Fused mean: partial sums + last-block reduce --------------
// Deterministic: partials indexed by blockIdx; last arriving block reduces
// them in fixed tree order. atomicInc wraps the ticket to 0 at grid end, so
// graph replays see identical initial state.
__global__ __launch_bounds__(256) void moran_mean_kernel(
    const float4* __restrict__ X4, int n4, int n) {
#if __CUDA_ARCH__ >= 900
    cudaTriggerProgrammaticLaunchCompletion();
#endif
    __shared__ float sh[256];
    float s0 = 0.0f, s1 = 0.0f, s2 = 0.0f, s3 = 0.0f;
    for (int i = blockIdx.x * blockDim.x + threadIdx.x; i < n4;
         i += gridDim.x * blockDim.x) {
        float4 v = X4[i];
        s0 += v.x; s1 += v.y; s2 += v.z; s3 += v.w;
    }
    sh[threadIdx.x] = (s0 + s1) + (s2 + s3);
    __syncthreads();
#pragma unroll
    for (int off = 128; off > 0; off >>= 1) {
        if (threadIdx.x < off) sh[threadIdx.x] += sh[threadIdx.x + off];
        __syncthreads();
    }

    __shared__ bool is_last;
    if (threadIdx.x == 0) {
        g_partials[blockIdx.x] = sh[0];
        __threadfence();
        unsigned int t = atomicInc(&g_ticket, MEAN_BLOCKS - 1);
        is_last = (t == MEAN_BLOCKS - 1);
    }
    __syncthreads();

    if (is_last) {
        float r = 0.0f;
#pragma unroll
        for (int j = 0; j < MEAN_BLOCKS / 256; j++)
            r += g_partials[threadIdx.x + j * 256];
        sh[threadIdx.x] = r;
        __syncthreads();
#pragma unroll
        for (int off = 128; off > 0; off >>= 1) {
            if (threadIdx.x < off) sh[threadIdx.x] += sh[threadIdx.x + off];
            __syncthreads();
        }
        if (threadIdx.x == 0) g_mean = sh[0] / (float)n;
    }
}

// ---------------- Main Local Moran kernel (flat launch, frozen layout) ------
// 4 rows per warp, 8 lanes per row. Lane l: row_local = l>>3, seg = l&7.
// W/IDS loads are 512B contiguous per warp instruction (4 wf for 4 rows).
// Load phase is mean-independent; mean is consumed only in the epilogue.
__global__ __launch_bounds__(256) void moran_main_kernel(
    const float* __restrict__ X,
    const float4* __restrict__ W,    // float4 view of [N, 32]
    const int4* __restrict__ IDS,    // int4 view of [N, 32]
    float* __restrict__ out, int n) {
    int warp_global = (blockIdx.x * blockDim.x + threadIdx.x) >> 5;
    int lane = threadIdx.x & 31;
    int row = warp_global * 4 + (lane >> 3);
    int seg = lane & 7;
    if (row >= n) return;

    size_t idx4 = (size_t)row * (KNBR / 4) + seg;

    // Coalesced streams (evict-first; X must stay L2-resident).
    float4 w = __ldcs(W + idx4);
    int4 id = __ldcs(IDS + idx4);

    // 4 random gathers per lane (irreducible wavefront cost). No mean needed.
    float x0 = __ldg(X + id.x);
    float x1 = __ldg(X + id.y);
    float x2 = __ldg(X + id.z);
    float x3 = __ldg(X + id.w);

    float t0 = w.x * x0;
    float t1 = w.y * x1;
    float t2 = w.z * x2;
    float t3 = w.w * x3;

    float A = (t0 + t1) + (t2 + t3);                               // sum w x
    float B = fmaf(t0, x0, fmaf(t1, x1, fmaf(t2, x2, t3 * x3)));   // sum w x^2
    float C = (w.x + w.y) + (w.z + w.w);                           // sum w

    // Reduce across the 8 lanes sharing this row (offsets 4,2,1 in-group).
#pragma unroll
    for (int off = 4; off > 0; off >>= 1) {
        A += __shfl_xor_sync(0xFFFFFFFFu, A, off);
        B += __shfl_xor_sync(0xFFFFFFFFu, B, off);
        C += __shfl_xor_sync(0xFFFFFFFFu, C, off);
    }

#if __CUDA_ARCH__ >= 900
    // Wait for the mean kernel (long since complete at this point).
    cudaGridDependencySynchronize();
#endif

    if (seg == 0) {
        float m = g_mean;
        float lag = fmaf(-m, C, A);                     // A - mC
        float S = fmaf(m, fmaf(m, C, -2.0f * A), B);    // B - 2mA + m^2 C
        float xa = __ldg(X + row) - m;
        out[row] = xa * lag * (float)(KNBR - 1) * __frcp_rn(S);
    }
}

extern "C" void kernel_launch(void* const* d_in, const int* in_sizes, int n_in,
                              void* d_out, int out_size) {
    const float* X = (const float*)d_in[0];
    const float* W = (const float*)d_in[1];
    const int* IDS = (const int*)d_in[2];
    float* out = (float*)d_out;
    int n = in_sizes[0];

    // Mean kernel (triggers programmatic launch completion at entry).
    moran_mean_kernel<<<MEAN_BLOCKS, 256>>>((const float4*)X, n / 4, n);

    // Main kernel with PDL: overlaps its load phase with the mean kernel.
    int threads = 256;
    int rows_per_block = (threads / 32) * 4;  // 32
    int blocks = (n + rows_per_block - 1) / rows_per_block;

    cudaLaunchAttribute attrs[1];
    attrs[0].id = cudaLaunchAttributeProgrammaticStreamSerialization;
    attrs[0].val.programmaticStreamSerializationAllowed = 1;

    cudaLaunchConfig_t cfg = {};
    cfg.gridDim = dim3(blocks, 1, 1);
    cfg.blockDim = dim3(threads, 1, 1);
    cfg.dynamicSmemBytes = 0;
    cfg.stream = 0;
    cfg.attrs = attrs;
    cfg.numAttrs = 1;

    cudaError_t err = cudaLaunchKernelEx(&cfg, moran_main_kernel,
                                         X, (const float4*)W, (const int4*)IDS,
                                         out, n);
    if (err != cudaSuccess) {
        // PDL attribute rejected (driver/capture path): plain serialized
        // launch. Results identical; the epilogue grid-sync is then a no-op
        // (the mean kernel has already completed in stream order).
        (void)cudaGetLastError();  // clear the sticky error
        moran_main_kernel<<<blocks, threads>>>(
            X, (const float4*)W, (const int4*)IDS, out, n);
    }
}